// round 7
// baseline (speedup 1.0000x reference)
#include <cuda_runtime.h>
#include <math_constants.h>

typedef unsigned long long u64;

#define NNODES   100000
#define EEDGES   1600000
#define TEDGES   (EEDGES + NNODES)
#define HEADS 4

// ---------------------------------------------------------------------------
// Device scratch (static; no cudaMalloc allowed)
// ---------------------------------------------------------------------------
__device__ float g_xl[NNODES * 256];
__device__ float g_xr[NNODES * 256];
__device__ float g_h [NNODES * 64];
__device__ int   g_ssrc[TEDGES];
__device__ int   g_cnt [NNODES];
__device__ int   g_cur [NNODES];
__device__ int   g_base[NNODES + 1];
__device__ int   g_bsum[128];
__device__ int   g_boff[128];

static inline int cdiv(int a, int b) { return (a + b - 1) / b; }

// ---------------------------------------------------------------------------
// Packed f32x2 helpers (Blackwell; only reachable via PTX)
// ---------------------------------------------------------------------------
__device__ __forceinline__ u64 pack2(float lo, float hi) {
    u64 r; asm("mov.b64 %0,{%1,%2};" : "=l"(r) : "f"(lo), "f"(hi)); return r;
}
__device__ __forceinline__ void unpack2(u64 v, float& lo, float& hi) {
    asm("mov.b64 {%0,%1},%2;" : "=f"(lo), "=f"(hi) : "l"(v));
}
__device__ __forceinline__ u64 add2(u64 a, u64 b) {
    u64 r; asm("add.rn.f32x2 %0,%1,%2;" : "=l"(r) : "l"(a), "l"(b)); return r;
}
__device__ __forceinline__ u64 fma2(u64 a, u64 b, u64 c) {
    u64 r; asm("fma.rn.f32x2 %0,%1,%2,%3;" : "=l"(r) : "l"(a), "l"(b), "l"(c)); return r;
}

// ---------------------------------------------------------------------------
// Edge-index dtype check (int64 vs int32): first 4 int64 reads must be in range
// ---------------------------------------------------------------------------
__device__ __forceinline__ bool ei_is64(const void* ei, int Nn) {
    const long long* p = (const long long*)ei;
    bool ok = true;
    #pragma unroll
    for (int i = 0; i < 4; i++) {
        long long v = __ldg(p + i);
        ok = ok && (v >= 0 && v < (long long)Nn);
    }
    return ok;
}

__global__ void init_cnt_kernel(int Nn) {
    int i = blockIdx.x * blockDim.x + threadIdx.x;
    if (i < Nn) g_cnt[i] = 1;          // implicit self loop
}

__global__ void hist_kernel(const void* ei, int E, int Nn) {
    int i = blockIdx.x * blockDim.x + threadIdx.x;
    if (i >= E) return;
    int d;
    if (ei_is64(ei, Nn)) d = (int)__ldg((const long long*)ei + E + i);
    else                 d = __ldg((const int*)ei + E + i);
    atomicAdd(&g_cnt[d], 1);
}

__global__ void scan1_kernel(int n) {
    __shared__ int sh[1024];
    int t = threadIdx.x;
    int i = blockIdx.x * 1024 + t;
    int v = (i < n) ? g_cnt[i] : 0;
    sh[t] = v;
    __syncthreads();
    for (int off = 1; off < 1024; off <<= 1) {
        int u = (t >= off) ? sh[t - off] : 0;
        __syncthreads();
        sh[t] += u;
        __syncthreads();
    }
    int incl = sh[t];
    if (i < n) g_base[i] = incl - v;
    if (t == 1023) g_bsum[blockIdx.x] = incl;
}

__global__ void scan2_kernel(int nb) {
    int lane = threadIdx.x;
    int carry = 0;
    for (int b = 0; b < nb; b += 32) {
        int i = b + lane;
        int orig = (i < nb) ? g_bsum[i] : 0;
        int v = orig;
        #pragma unroll
        for (int off = 1; off < 32; off <<= 1) {
            int u = __shfl_up_sync(0xffffffffu, v, off);
            if (lane >= off) v += u;
        }
        if (i < nb) g_boff[i] = carry + v - orig;
        carry += __shfl_sync(0xffffffffu, v, 31);
    }
}

__global__ void scan3_kernel(int n, int total) {
    int i = blockIdx.x * 1024 + threadIdx.x;
    if (i < n) {
        int b = g_base[i] + g_boff[blockIdx.x];
        g_base[i] = b;
        g_cur[i]  = b;
    }
    if (i == 0) g_base[n] = total;
}

__global__ void scatter_kernel(const void* ei, int E, int Nn) {
    int i = blockIdx.x * blockDim.x + threadIdx.x;
    if (i >= E + Nn) return;
    int s, d;
    if (i < E) {
        if (ei_is64(ei, Nn)) {
            const long long* p = (const long long*)ei;
            s = (int)__ldg(p + i); d = (int)__ldg(p + E + i);
        } else {
            const int* p = (const int*)ei;
            s = __ldg(p + i); d = __ldg(p + E + i);
        }
    } else {
        s = d = i - E;
    }
    int pos = atomicAdd(&g_cur[d], 1);
    g_ssrc[pos] = s;
}

// ---------------------------------------------------------------------------
// tf32 helpers + dual GEMM (proven R3 config: 3xTF32, fp32 in/out)
// ---------------------------------------------------------------------------
__device__ __forceinline__ unsigned f2tf32(float x) {
    unsigned u;
    asm("cvt.rna.tf32.f32 %0, %1;" : "=r"(u) : "f"(x));
    return u;
}

__device__ __forceinline__ void mma_m16n8k8(float* d, const unsigned* a, const unsigned* b) {
    asm volatile(
        "mma.sync.aligned.m16n8k8.row.col.f32.tf32.tf32.f32 "
        "{%0,%1,%2,%3}, {%4,%5,%6,%7}, {%8,%9}, {%0,%1,%2,%3};\n"
        : "+f"(d[0]), "+f"(d[1]), "+f"(d[2]), "+f"(d[3])
        : "r"(a[0]), "r"(a[1]), "r"(a[2]), "r"(a[3]),
          "r"(b[0]), "r"(b[1]));
}

__global__ void dual_gemm_tf32(const float* __restrict__ A,
                               const float* __restrict__ Wl, const float* __restrict__ bl,
                               const float* __restrict__ Wr, const float* __restrict__ br,
                               float* __restrict__ Cl, float* __restrict__ Cr,
                               int M, int Nc) {
    extern __shared__ float sm[];
    float* As = sm;               // [128][65]
    float* Bs = sm + 128 * 65;    // [64][65]  as [n][k]
    const int tid  = threadIdx.x;
    const int warp = tid >> 5, lane = tid & 31;
    const int g = lane >> 2, c = lane & 3;
    const int row0 = blockIdx.y * 128;
    const int col0 = blockIdx.x * 64;

    const float* W; const float* bias; float* C; int cofs;
    if (col0 < Nc) { W = Wl; bias = bl; C = Cl; cofs = col0; }
    else           { W = Wr; bias = br; C = Cr; cofs = col0 - Nc; }

    #pragma unroll
    for (int i = 0; i < 8; i++) {
        int idx = tid + i * 256;
        int r = idx >> 4, c4 = (idx & 15) << 2;
        int row = row0 + r;
        float4 v = make_float4(0.f, 0.f, 0.f, 0.f);
        if (row < M)
            v = *reinterpret_cast<const float4*>(A + (size_t)row * 64 + c4);
        float* dst = As + r * 65 + c4;
        dst[0] = v.x; dst[1] = v.y; dst[2] = v.z; dst[3] = v.w;
    }
    #pragma unroll
    for (int i = 0; i < 4; i++) {
        int idx = tid + i * 256;
        int k = idx >> 4, c4 = (idx & 15) << 2;
        float4 v = *reinterpret_cast<const float4*>(W + (size_t)k * Nc + cofs + c4);
        Bs[(c4 + 0) * 65 + k] = v.x;
        Bs[(c4 + 1) * 65 + k] = v.y;
        Bs[(c4 + 2) * 65 + k] = v.z;
        Bs[(c4 + 3) * 65 + k] = v.w;
    }
    __syncthreads();

    float acc[8][4];
    #pragma unroll
    for (int n = 0; n < 8; n++)
        #pragma unroll
        for (int j = 0; j < 4; j++) acc[n][j] = 0.f;

    const int wr = warp * 16;
    #pragma unroll
    for (int kk = 0; kk < 8; kk++) {
        const int k0 = kk * 8;
        float a_f[4];
        a_f[0] = As[(wr + g)     * 65 + k0 + c];
        a_f[1] = As[(wr + g + 8) * 65 + k0 + c];
        a_f[2] = As[(wr + g)     * 65 + k0 + c + 4];
        a_f[3] = As[(wr + g + 8) * 65 + k0 + c + 4];
        unsigned ahi[4], alo[4];
        #pragma unroll
        for (int j = 0; j < 4; j++) {
            ahi[j] = f2tf32(a_f[j]);
            alo[j] = f2tf32(a_f[j] - __uint_as_float(ahi[j]));
        }
        #pragma unroll
        for (int n = 0; n < 8; n++) {
            float b0 = Bs[(n * 8 + g) * 65 + k0 + c];
            float b1 = Bs[(n * 8 + g) * 65 + k0 + c + 4];
            unsigned bhi[2], blo[2];
            bhi[0] = f2tf32(b0);
            bhi[1] = f2tf32(b1);
            blo[0] = f2tf32(b0 - __uint_as_float(bhi[0]));
            blo[1] = f2tf32(b1 - __uint_as_float(bhi[1]));
            mma_m16n8k8(acc[n], ahi, bhi);
            mma_m16n8k8(acc[n], alo, bhi);
            mma_m16n8k8(acc[n], ahi, blo);
        }
    }

    #pragma unroll
    for (int n = 0; n < 8; n++) {
        int colg = cofs + n * 8 + 2 * c;
        float bx = __ldg(bias + colg);
        float by = __ldg(bias + colg + 1);
        int r1 = row0 + wr + g, r2 = r1 + 8;
        if (r1 < M)
            *reinterpret_cast<float2*>(C + (size_t)r1 * Nc + colg) =
                make_float2(acc[n][0] + bx, acc[n][1] + by);
        if (r2 < M)
            *reinterpret_cast<float2*>(C + (size_t)r2 * Nc + colg) =
                make_float2(acc[n][2] + bx, acc[n][3] + by);
    }
}

// ---------------------------------------------------------------------------
// Layer-1 fused GAT: D=64, warp per dst node, TWO edges per iteration
// (16 lanes per edge), no-max online softmax, packed f32x2 math.
// ---------------------------------------------------------------------------
__global__ void fused_gat_l1(const float* __restrict__ att,
                             const float* __restrict__ bo,
                             float* __restrict__ outp, int Nn) {
    int w = (blockIdx.x * blockDim.x + threadIdx.x) >> 5;
    int lane = threadIdx.x & 31;
    if (w >= Nn) return;
    const int sub = lane >> 4;        // which edge of the pair
    const int sl  = lane & 15;
    const int f0  = sl * 4;           // 4 features per lane; head = sl>>2

    const int beg = g_base[w], end = g_base[w + 1];

    float4 vrf = *reinterpret_cast<const float4*>(g_xr + (size_t)w * 64 + f0);
    u64 vr2[2] = { pack2(vrf.x, vrf.y), pack2(vrf.z, vrf.w) };
    u64 av06[2], av04[2];
    #pragma unroll
    for (int j = 0; j < 2; j++) {
        float a0 = __ldg(att + f0 + 2 * j);
        float a1 = __ldg(att + f0 + 2 * j + 1);
        av06[j] = pack2(0.6f * a0, 0.6f * a1);
        av04[j] = pack2(0.4f * a0, 0.4f * a1);
    }

    float l = 0.f;
    u64 acc2[2] = {0ull, 0ull};

    // depth-1 prefetch
    u64 vl2[2];
    {
        int e = beg + sub;
        int idx = __ldg(g_ssrc + (e < end ? e : end - 1));
        float4 t = *reinterpret_cast<const float4*>(g_xl + (size_t)idx * 64 + f0);
        vl2[0] = pack2(t.x, t.y); vl2[1] = pack2(t.z, t.w);
    }

    for (int p = beg; p < end; p += 2) {
        u64 cv0 = vl2[0], cv1 = vl2[1];
        bool valid = (p + sub) < end;
        int np = p + 2 + sub;
        if (np < end) {
            int idx = __ldg(g_ssrc + np);
            float4 t = *reinterpret_cast<const float4*>(g_xl + (size_t)idx * 64 + f0);
            vl2[0] = pack2(t.x, t.y); vl2[1] = pack2(t.z, t.w);
        }
        u64 p2 = 0ull;
        {
            u64 v = add2(cv0, vr2[0]);
            u64 a = v & 0x7FFFFFFF7FFFFFFFull;
            p2 = fma2(av06[0], v, p2);
            p2 = fma2(av04[0], a, p2);
            v = add2(cv1, vr2[1]);
            a = v & 0x7FFFFFFF7FFFFFFFull;
            p2 = fma2(av06[1], v, p2);
            p2 = fma2(av04[1], a, p2);
        }
        float plo, phi; unpack2(p2, plo, phi);
        float s = plo + phi;
        s += __shfl_xor_sync(0xffffffffu, s, 1);
        s += __shfl_xor_sync(0xffffffffu, s, 2);
        float pe = valid ? __expf(s) : 0.f;
        l += pe;
        u64 pe2 = pack2(pe, pe);
        acc2[0] = fma2(pe2, cv0, acc2[0]);
        acc2[1] = fma2(pe2, cv1, acc2[1]);
    }

    // combine the two half-warps
    l += __shfl_xor_sync(0xffffffffu, l, 16);
    float a[4];
    unpack2(acc2[0], a[0], a[1]);
    unpack2(acc2[1], a[2], a[3]);
    #pragma unroll
    for (int j = 0; j < 4; j++)
        a[j] += __shfl_xor_sync(0xffffffffu, a[j], 16);

    if (sub == 0) {
        float inv = 1.f / (l + 1e-16f);
        float4 o;
        o.x = fmaxf(fmaf(a[0], inv, __ldg(bo + f0 + 0)), 0.f);
        o.y = fmaxf(fmaf(a[1], inv, __ldg(bo + f0 + 1)), 0.f);
        o.z = fmaxf(fmaf(a[2], inv, __ldg(bo + f0 + 2)), 0.f);
        o.w = fmaxf(fmaf(a[3], inv, __ldg(bo + f0 + 3)), 0.f);
        *reinterpret_cast<float4*>(outp + (size_t)w * 64 + f0) = o;
    }
}

// ---------------------------------------------------------------------------
// Layer-2 fused GAT: D=256, warp per dst node, one edge per iteration,
// 8 lanes per head / 8 features per lane, no-max softmax, packed f32x2.
// Mean over heads + bias + relu epilogue.
// ---------------------------------------------------------------------------
__global__ void fused_gat_l2(const float* __restrict__ att,
                             const float* __restrict__ bo,
                             float* __restrict__ outp, int Nn) {
    int w = (blockIdx.x * blockDim.x + threadIdx.x) >> 5;
    int lane = threadIdx.x & 31;
    if (w >= Nn) return;
    const int f0 = lane * 8;          // head = lane>>3

    const int beg = g_base[w], end = g_base[w + 1];

    u64 vr2[4], av06[4], av04[4];
    {
        const float* xr = g_xr + (size_t)w * 256 + f0;
        float4 t0 = *reinterpret_cast<const float4*>(xr);
        float4 t1 = *reinterpret_cast<const float4*>(xr + 4);
        vr2[0] = pack2(t0.x, t0.y); vr2[1] = pack2(t0.z, t0.w);
        vr2[2] = pack2(t1.x, t1.y); vr2[3] = pack2(t1.z, t1.w);
    }
    #pragma unroll
    for (int j = 0; j < 4; j++) {
        float a0 = __ldg(att + f0 + 2 * j);
        float a1 = __ldg(att + f0 + 2 * j + 1);
        av06[j] = pack2(0.6f * a0, 0.6f * a1);
        av04[j] = pack2(0.4f * a0, 0.4f * a1);
    }

    float l = 0.f;
    u64 acc2[4] = {0ull, 0ull, 0ull, 0ull};

    u64 vl2[4];
    if (beg < end) {
        int idx = __ldg(g_ssrc + beg);
        const float* xl = g_xl + (size_t)idx * 256 + f0;
        float4 t0 = *reinterpret_cast<const float4*>(xl);
        float4 t1 = *reinterpret_cast<const float4*>(xl + 4);
        vl2[0] = pack2(t0.x, t0.y); vl2[1] = pack2(t0.z, t0.w);
        vl2[2] = pack2(t1.x, t1.y); vl2[3] = pack2(t1.z, t1.w);
    }

    for (int p = beg; p < end; p++) {
        u64 cv[4];
        #pragma unroll
        for (int j = 0; j < 4; j++) cv[j] = vl2[j];
        if (p + 1 < end) {
            int idx = __ldg(g_ssrc + p + 1);
            const float* xl = g_xl + (size_t)idx * 256 + f0;
            float4 t0 = *reinterpret_cast<const float4*>(xl);
            float4 t1 = *reinterpret_cast<const float4*>(xl + 4);
            vl2[0] = pack2(t0.x, t0.y); vl2[1] = pack2(t0.z, t0.w);
            vl2[2] = pack2(t1.x, t1.y); vl2[3] = pack2(t1.z, t1.w);
        }
        u64 p2 = 0ull;
        #pragma unroll
        for (int j = 0; j < 4; j++) {
            u64 v = add2(cv[j], vr2[j]);
            u64 a = v & 0x7FFFFFFF7FFFFFFFull;
            p2 = fma2(av06[j], v, p2);
            p2 = fma2(av04[j], a, p2);
        }
        float plo, phi; unpack2(p2, plo, phi);
        float s = plo + phi;
        s += __shfl_xor_sync(0xffffffffu, s, 1);
        s += __shfl_xor_sync(0xffffffffu, s, 2);
        s += __shfl_xor_sync(0xffffffffu, s, 4);
        float pe = __expf(s);
        l += pe;
        u64 pe2 = pack2(pe, pe);
        #pragma unroll
        for (int j = 0; j < 4; j++)
            acc2[j] = fma2(pe2, cv[j], acc2[j]);
    }

    float inv = 1.f / (l + 1e-16f);
    float a[8];
    #pragma unroll
    for (int j = 0; j < 4; j++) unpack2(acc2[j], a[2 * j], a[2 * j + 1]);
    #pragma unroll
    for (int j = 0; j < 8; j++) {
        a[j] *= inv;
        a[j] += __shfl_xor_sync(0xffffffffu, a[j], 8);
        a[j] += __shfl_xor_sync(0xffffffffu, a[j], 16);
    }
    if (lane < 8) {
        float o[8];
        #pragma unroll
        for (int j = 0; j < 8; j++) {
            float v = fmaf(0.25f, a[j], __ldg(bo + f0 + j));
            o[j] = fmaxf(v, 0.f);
        }
        float* dst = outp + (size_t)w * 64 + f0;
        *reinterpret_cast<float4*>(dst)     = make_float4(o[0], o[1], o[2], o[3]);
        *reinterpret_cast<float4*>(dst + 4) = make_float4(o[4], o[5], o[6], o[7]);
    }
}

// ---------------------------------------------------------------------------
// Host launcher
// ---------------------------------------------------------------------------
extern "C" void kernel_launch(void* const* d_in, const int* in_sizes, int n_in,
                              void* d_out, int out_size) {
    const float* x   = (const float*)d_in[0];
    const void*  ei  = d_in[1];
    const float* Wl1 = (const float*)d_in[3];
    const float* bl1 = (const float*)d_in[4];
    const float* Wr1 = (const float*)d_in[5];
    const float* br1 = (const float*)d_in[6];
    const float* att1= (const float*)d_in[7];
    const float* bo1 = (const float*)d_in[8];
    const float* Wl2 = (const float*)d_in[9];
    const float* bl2 = (const float*)d_in[10];
    const float* Wr2 = (const float*)d_in[11];
    const float* br2 = (const float*)d_in[12];
    const float* att2= (const float*)d_in[13];
    const float* bo2 = (const float*)d_in[14];
    float* out = (float*)d_out;

    const int N = in_sizes[0] / 64;
    const int E = in_sizes[1] / 2;
    const int TE = E + N;

    float *p_xl, *p_xr, *p_h;
    cudaGetSymbolAddress((void**)&p_xl, g_xl);
    cudaGetSymbolAddress((void**)&p_xr, g_xr);
    cudaGetSymbolAddress((void**)&p_h,  g_h);

    const int TB = 256;
    const int SMEM_GEMM = (128 * 65 + 64 * 65) * 4;
    static int attrSet = 0;
    if (!attrSet) {
        cudaFuncSetAttribute(dual_gemm_tf32,
                             cudaFuncAttributeMaxDynamicSharedMemorySize, SMEM_GEMM);
        attrSet = 1;
    }

    int fusedBlocks = cdiv(N, TB / 32);
    int nScanBlocks = cdiv(N, 1024);

    // ---- build dst-sorted edge CSR ----
    init_cnt_kernel<<<cdiv(N, TB), TB>>>(N);
    hist_kernel<<<cdiv(E, TB), TB>>>(ei, E, N);
    scan1_kernel<<<nScanBlocks, 1024>>>(N);
    scan2_kernel<<<1, 32>>>(nScanBlocks);
    scan3_kernel<<<nScanBlocks, 1024>>>(N, TE);
    scatter_kernel<<<cdiv(TE, TB), TB>>>(ei, E, N);

    // ---- layer 1: dual GEMM (Nc=64) + fused GAT ----
    dim3 g1(2, cdiv(N, 128));
    dual_gemm_tf32<<<g1, TB, SMEM_GEMM>>>(x, Wl1, bl1, Wr1, br1, p_xl, p_xr, N, 64);
    fused_gat_l1<<<fusedBlocks, TB>>>(att1, bo1, p_h, N);

    // ---- layer 2: dual GEMM (Nc=256) + fused GAT ----
    dim3 g2(8, cdiv(N, 128));
    dual_gemm_tf32<<<g2, TB, SMEM_GEMM>>>(p_h, Wl2, bl2, Wr2, br2, p_xl, p_xr, N, 256);
    fused_gat_l2<<<fusedBlocks, TB>>>(att2, bo2, out, N);
}

// round 8
// speedup vs baseline: 1.2045x; 1.2045x over previous
#include <cuda_runtime.h>
#include <cuda_fp16.h>
#include <cuda_bf16.h>
#include <math_constants.h>

#define NNODES   100000
#define EEDGES   1600000
#define TEDGES   (EEDGES + NNODES)
#define NEG_SLOPE 0.2f
#define HEADS 4

// ---------------------------------------------------------------------------
// Device scratch (static; no cudaMalloc allowed)
// ---------------------------------------------------------------------------
__device__ uint4 g_xlh_raw[NNODES * 256 * 2 / 16];  // xl as fp16
__device__ float g_xr[NNODES * 256];
__device__ float g_h [NNODES * 64];
__device__ int   g_src [EEDGES];
__device__ int   g_dst [EEDGES];
__device__ int   g_ssrc[TEDGES];
__device__ int   g_cnt [NNODES];
__device__ int   g_cur [NNODES];
__device__ int   g_base[NNODES + 1];
__device__ int   g_bsum[128];
__device__ int   g_boff[128];
__device__ int   g_is64;

static inline int cdiv(int a, int b) { return (a + b - 1) / b; }

// ---------------------------------------------------------------------------
// Edge-index dtype detect + CSR build (R4 path, init race fixed)
// ---------------------------------------------------------------------------
__global__ void detect_kernel(const void* ei, int nCheck, long long nNodes) {
    const long long* p = (const long long*)ei;
    int ok = 1;
    for (int i = 0; i < nCheck; i++) {
        long long v = p[i];
        if (v < 0 || v >= nNodes) { ok = 0; break; }
    }
    g_is64 = ok;
}

__global__ void init_cnt_kernel(int Nn) {
    int i = blockIdx.x * blockDim.x + threadIdx.x;
    if (i < Nn) g_cnt[i] = 1;          // implicit self loop
}

__global__ void convert_hist_kernel(const void* ei, int E) {
    int i = blockIdx.x * blockDim.x + threadIdx.x;
    if (i >= E) return;
    int s, d;
    if (g_is64) {
        const long long* p = (const long long*)ei;
        s = (int)p[i]; d = (int)p[E + i];
    } else {
        const int* p = (const int*)ei;
        s = p[i]; d = p[E + i];
    }
    g_src[i] = s;
    g_dst[i] = d;
    atomicAdd(&g_cnt[d], 1);
}

__global__ void scan1_kernel(int n) {
    __shared__ int sh[1024];
    int t = threadIdx.x;
    int i = blockIdx.x * 1024 + t;
    int v = (i < n) ? g_cnt[i] : 0;
    sh[t] = v;
    __syncthreads();
    for (int off = 1; off < 1024; off <<= 1) {
        int u = (t >= off) ? sh[t - off] : 0;
        __syncthreads();
        sh[t] += u;
        __syncthreads();
    }
    int incl = sh[t];
    if (i < n) g_base[i] = incl - v;
    if (t == 1023) g_bsum[blockIdx.x] = incl;
}

__global__ void scan2_kernel(int nb) {
    int lane = threadIdx.x;
    int carry = 0;
    for (int b = 0; b < nb; b += 32) {
        int i = b + lane;
        int orig = (i < nb) ? g_bsum[i] : 0;
        int v = orig;
        #pragma unroll
        for (int off = 1; off < 32; off <<= 1) {
            int u = __shfl_up_sync(0xffffffffu, v, off);
            if (lane >= off) v += u;
        }
        if (i < nb) g_boff[i] = carry + v - orig;
        carry += __shfl_sync(0xffffffffu, v, 31);
    }
}

__global__ void scan3_kernel(int n, int total) {
    int i = blockIdx.x * 1024 + threadIdx.x;
    if (i < n) {
        int b = g_base[i] + g_boff[blockIdx.x];
        g_base[i] = b;
        g_cur[i]  = b;
    }
    if (i == 0) g_base[n] = total;
}

__global__ void scatter_kernel(int E, int total) {
    int i = blockIdx.x * blockDim.x + threadIdx.x;
    if (i >= total) return;
    int s, d;
    if (i < E) { s = g_src[i]; d = g_dst[i]; }
    else       { s = d = i - E; }
    int pos = atomicAdd(&g_cur[d], 1);
    g_ssrc[pos] = s;
}

// ---------------------------------------------------------------------------
// bf16 m16n8k16 mma
// ---------------------------------------------------------------------------
__device__ __forceinline__ void mma_bf16(float* d, const unsigned* a, const unsigned* b) {
    asm volatile(
        "mma.sync.aligned.m16n8k16.row.col.f32.bf16.bf16.f32 "
        "{%0,%1,%2,%3}, {%4,%5,%6,%7}, {%8,%9}, {%0,%1,%2,%3};\n"
        : "+f"(d[0]), "+f"(d[1]), "+f"(d[2]), "+f"(d[3])
        : "r"(a[0]), "r"(a[1]), "r"(a[2]), "r"(a[3]),
          "r"(b[0]), "r"(b[1]));
}

// ---------------------------------------------------------------------------
// Dual GEMM, 3x-split bf16 tensor cores, fp32-grade accuracy.
// Cl = A@Wl + bl (fp16 out), Cr = A@Wr + br (fp32 out). K=64 fixed.
// BM=128, BN=64, 256 threads. hi/lo split precomputed in smem at load.
// Block x in [0, 2*Nc/64): first half -> Wl/Cl slice, second -> Wr/Cr.
// smem (bf16, pitch 72): As_hi[128], As_lo[128], Bs_hi[64], Bs_lo[64] rows.
// ---------------------------------------------------------------------------
#define AP 72
__global__ __launch_bounds__(256)
void dual_gemm_bf16(const float* __restrict__ A,
                    const float* __restrict__ Wl, const float* __restrict__ bl,
                    const float* __restrict__ Wr, const float* __restrict__ br,
                    __half* __restrict__ Cl, float* __restrict__ Cr,
                    int M, int Nc) {
    extern __shared__ __nv_bfloat16 smb[];
    __nv_bfloat16* As_hi = smb;
    __nv_bfloat16* As_lo = smb + 128 * AP;
    __nv_bfloat16* Bs_hi = smb + 256 * AP;
    __nv_bfloat16* Bs_lo = smb + 320 * AP;

    const int tid  = threadIdx.x;
    const int warp = tid >> 5, lane = tid & 31;
    const int g = lane >> 2, c = lane & 3;
    const int row0 = blockIdx.y * 128;
    const int col0 = blockIdx.x * 64;

    const bool isL = (col0 < Nc);
    const float* W    = isL ? Wl : Wr;
    const float* bias = isL ? bl : br;
    const int cofs = isL ? col0 : col0 - Nc;

    // A tile: 128 rows x 64 cols, split to bf16 hi/lo
    #pragma unroll
    for (int i = 0; i < 8; i++) {
        int idx = tid + i * 256;
        int r = idx >> 4, c4 = (idx & 15) << 2;
        int row = row0 + r;
        float4 v = make_float4(0.f, 0.f, 0.f, 0.f);
        if (row < M)
            v = *reinterpret_cast<const float4*>(A + (size_t)row * 64 + c4);
        float vv[4] = {v.x, v.y, v.z, v.w};
        #pragma unroll
        for (int j = 0; j < 4; j++) {
            __nv_bfloat16 hi = __float2bfloat16_rn(vv[j]);
            As_hi[r * AP + c4 + j] = hi;
            As_lo[r * AP + c4 + j] = __float2bfloat16_rn(vv[j] - __bfloat162float(hi));
        }
    }
    // B tile: W[k][cofs+..] -> Bs[n][k] transposed, split hi/lo
    #pragma unroll
    for (int i = 0; i < 4; i++) {
        int idx = tid + i * 256;
        int k = idx >> 4, c4 = (idx & 15) << 2;
        float4 v = *reinterpret_cast<const float4*>(W + (size_t)k * Nc + cofs + c4);
        float vv[4] = {v.x, v.y, v.z, v.w};
        #pragma unroll
        for (int j = 0; j < 4; j++) {
            __nv_bfloat16 hi = __float2bfloat16_rn(vv[j]);
            Bs_hi[(c4 + j) * AP + k] = hi;
            Bs_lo[(c4 + j) * AP + k] = __float2bfloat16_rn(vv[j] - __bfloat162float(hi));
        }
    }
    __syncthreads();

    float acc[8][4];
    #pragma unroll
    for (int n = 0; n < 8; n++)
        #pragma unroll
        for (int j = 0; j < 4; j++) acc[n][j] = 0.f;

    const int wr = warp * 16;
    #pragma unroll
    for (int kk = 0; kk < 4; kk++) {      // K=64, 16 per mma
        const int k0 = kk * 16;
        unsigned ahi[4], alo[4];
        {
            int r1 = (wr + g) * AP, r2 = (wr + g + 8) * AP;
            ahi[0] = *reinterpret_cast<const unsigned*>(&As_hi[r1 + k0 + 2 * c]);
            ahi[1] = *reinterpret_cast<const unsigned*>(&As_hi[r2 + k0 + 2 * c]);
            ahi[2] = *reinterpret_cast<const unsigned*>(&As_hi[r1 + k0 + 8 + 2 * c]);
            ahi[3] = *reinterpret_cast<const unsigned*>(&As_hi[r2 + k0 + 8 + 2 * c]);
            alo[0] = *reinterpret_cast<const unsigned*>(&As_lo[r1 + k0 + 2 * c]);
            alo[1] = *reinterpret_cast<const unsigned*>(&As_lo[r2 + k0 + 2 * c]);
            alo[2] = *reinterpret_cast<const unsigned*>(&As_lo[r1 + k0 + 8 + 2 * c]);
            alo[3] = *reinterpret_cast<const unsigned*>(&As_lo[r2 + k0 + 8 + 2 * c]);
        }
        #pragma unroll
        for (int n = 0; n < 8; n++) {
            int bro = (n * 8 + g) * AP;
            unsigned bhi[2], blo[2];
            bhi[0] = *reinterpret_cast<const unsigned*>(&Bs_hi[bro + k0 + 2 * c]);
            bhi[1] = *reinterpret_cast<const unsigned*>(&Bs_hi[bro + k0 + 8 + 2 * c]);
            blo[0] = *reinterpret_cast<const unsigned*>(&Bs_lo[bro + k0 + 2 * c]);
            blo[1] = *reinterpret_cast<const unsigned*>(&Bs_lo[bro + k0 + 8 + 2 * c]);
            mma_bf16(acc[n], ahi, bhi);
            mma_bf16(acc[n], alo, bhi);
            mma_bf16(acc[n], ahi, blo);
        }
    }

    #pragma unroll
    for (int n = 0; n < 8; n++) {
        int colg = cofs + n * 8 + 2 * c;
        float bx = __ldg(bias + colg);
        float by = __ldg(bias + colg + 1);
        int r1 = row0 + wr + g, r2 = r1 + 8;
        if (isL) {
            if (r1 < M)
                *reinterpret_cast<__half2*>(Cl + (size_t)r1 * Nc + colg) =
                    __floats2half2_rn(acc[n][0] + bx, acc[n][1] + by);
            if (r2 < M)
                *reinterpret_cast<__half2*>(Cl + (size_t)r2 * Nc + colg) =
                    __floats2half2_rn(acc[n][2] + bx, acc[n][3] + by);
        } else {
            if (r1 < M)
                *reinterpret_cast<float2*>(Cr + (size_t)r1 * Nc + colg) =
                    make_float2(acc[n][0] + bx, acc[n][1] + by);
            if (r2 < M)
                *reinterpret_cast<float2*>(Cr + (size_t)r2 * Nc + colg) =
                    make_float2(acc[n][2] + bx, acc[n][3] + by);
        }
    }
}

// ---------------------------------------------------------------------------
// Load helpers
// ---------------------------------------------------------------------------
template<int PE>
__device__ __forceinline__ void loadVec(const float* __restrict__ p, float* v) {
    if constexpr (PE % 4 == 0) {
        #pragma unroll
        for (int j = 0; j < PE / 4; j++) {
            float4 t = __ldg(reinterpret_cast<const float4*>(p) + j);
            v[j * 4 + 0] = t.x; v[j * 4 + 1] = t.y;
            v[j * 4 + 2] = t.z; v[j * 4 + 3] = t.w;
        }
    } else {
        float2 t = __ldg(reinterpret_cast<const float2*>(p));
        v[0] = t.x; v[1] = t.y;
    }
}

template<int PE>
__device__ __forceinline__ void loadVecH(const __half* __restrict__ p, float* v) {
    if constexpr (PE == 8) {
        uint4 t = __ldg(reinterpret_cast<const uint4*>(p));
        float2 f;
        f = __half22float2(*reinterpret_cast<__half2*>(&t.x)); v[0] = f.x; v[1] = f.y;
        f = __half22float2(*reinterpret_cast<__half2*>(&t.y)); v[2] = f.x; v[3] = f.y;
        f = __half22float2(*reinterpret_cast<__half2*>(&t.z)); v[4] = f.x; v[5] = f.y;
        f = __half22float2(*reinterpret_cast<__half2*>(&t.w)); v[6] = f.x; v[7] = f.y;
    } else {
        unsigned t = __ldg(reinterpret_cast<const unsigned*>(p));
        float2 f = __half22float2(*reinterpret_cast<__half2*>(&t));
        v[0] = f.x; v[1] = f.y;
    }
}

// ---------------------------------------------------------------------------
// Fused GATv2 edge pass (R4-proven): warp per dst node, online softmax,
// depth-1 prefetch, xl in fp16, xr fp32, all math fp32.
// ---------------------------------------------------------------------------
template<int CC, bool MEAN>
__global__ void fused_gat_kernel(const float* __restrict__ att,
                                 const float* __restrict__ bo,
                                 float* __restrict__ outp, int Nn) {
    constexpr int D = HEADS * CC;
    constexpr int PE = D / 32;
    int w = (blockIdx.x * blockDim.x + threadIdx.x) >> 5;
    int lane = threadIdx.x & 31;
    if (w >= Nn) return;

    const __half* xlh = reinterpret_cast<const __half*>(g_xlh_raw);
    const int f0 = lane * PE;
    const int beg = g_base[w];
    const int end = g_base[w + 1];

    float vr[PE], av[PE];
    loadVec<PE>(g_xr + (size_t)w * D + f0, vr);
    #pragma unroll
    for (int j = 0; j < PE; j++) av[j] = __ldg(att + f0 + j);

    float m = -CUDART_INF_F, l = 0.f;
    float acc[PE];
    #pragma unroll
    for (int j = 0; j < PE; j++) acc[j] = 0.f;

    float vl[PE];
    if (beg < end) {
        int s0 = __ldg(g_ssrc + beg);
        loadVecH<PE>(xlh + (size_t)s0 * D + f0, vl);
    }

    for (int p = beg; p < end; p++) {
        float cvl[PE];
        #pragma unroll
        for (int j = 0; j < PE; j++) cvl[j] = vl[j];
        if (p + 1 < end) {
            int sn = __ldg(g_ssrc + p + 1);
            loadVecH<PE>(xlh + (size_t)sn * D + f0, vl);
        }
        float partial = 0.f;
        #pragma unroll
        for (int j = 0; j < PE; j++) {
            float v = cvl[j] + vr[j];
            v = (v > 0.f) ? v : NEG_SLOPE * v;
            partial = fmaf(av[j], v, partial);
        }
        #pragma unroll
        for (int off = 4; off; off >>= 1)
            partial += __shfl_xor_sync(0xffffffffu, partial, off);

        float mn = fmaxf(m, partial);
        float scale = __expf(m - mn);
        float pe = __expf(partial - mn);
        l = l * scale + pe;
        #pragma unroll
        for (int j = 0; j < PE; j++)
            acc[j] = acc[j] * scale + pe * cvl[j];
        m = mn;
    }

    float inv = 1.f / (l + 1e-16f);

    if constexpr (!MEAN) {
        float2 o;
        o.x = acc[0] * inv + __ldg(bo + f0 + 0);
        o.y = acc[1] * inv + __ldg(bo + f0 + 1);
        o.x = (o.x > 0.f) ? o.x : 0.f;
        o.y = (o.y > 0.f) ? o.y : 0.f;
        *reinterpret_cast<float2*>(outp + (size_t)w * D + f0) = o;
    } else {
        #pragma unroll
        for (int j = 0; j < PE; j++) acc[j] *= inv;
        #pragma unroll
        for (int j = 0; j < PE; j++) {
            acc[j] += __shfl_xor_sync(0xffffffffu, acc[j], 8);
            acc[j] += __shfl_xor_sync(0xffffffffu, acc[j], 16);
        }
        if (lane < 8) {
            float o[PE];
            #pragma unroll
            for (int j = 0; j < PE; j++) {
                float v = 0.25f * acc[j] + __ldg(bo + f0 + j);
                o[j] = (v > 0.f) ? v : 0.f;
            }
            #pragma unroll
            for (int j = 0; j < PE / 4; j++)
                *reinterpret_cast<float4*>(outp + (size_t)w * 64 + f0 + j * 4) =
                    make_float4(o[j*4], o[j*4+1], o[j*4+2], o[j*4+3]);
        }
    }
}

// ---------------------------------------------------------------------------
// Host launcher
// ---------------------------------------------------------------------------
extern "C" void kernel_launch(void* const* d_in, const int* in_sizes, int n_in,
                              void* d_out, int out_size) {
    const float* x   = (const float*)d_in[0];
    const void*  ei  = d_in[1];
    const float* Wl1 = (const float*)d_in[3];
    const float* bl1 = (const float*)d_in[4];
    const float* Wr1 = (const float*)d_in[5];
    const float* br1 = (const float*)d_in[6];
    const float* att1= (const float*)d_in[7];
    const float* bo1 = (const float*)d_in[8];
    const float* Wl2 = (const float*)d_in[9];
    const float* bl2 = (const float*)d_in[10];
    const float* Wr2 = (const float*)d_in[11];
    const float* br2 = (const float*)d_in[12];
    const float* att2= (const float*)d_in[13];
    const float* bo2 = (const float*)d_in[14];
    float* out = (float*)d_out;

    const int N = in_sizes[0] / 64;
    const int E = in_sizes[1] / 2;
    const int TE = E + N;

    __half* p_xlh; float* p_xr; float* p_h;
    cudaGetSymbolAddress((void**)&p_xlh, g_xlh_raw);
    cudaGetSymbolAddress((void**)&p_xr,  g_xr);
    cudaGetSymbolAddress((void**)&p_h,   g_h);

    const int TB = 256;
    const int SMEM_GEMM = 384 * AP * 2;   // 55296 B
    static int attrSet = 0;
    if (!attrSet) {
        cudaFuncSetAttribute(dual_gemm_bf16,
                             cudaFuncAttributeMaxDynamicSharedMemorySize, SMEM_GEMM);
        attrSet = 1;
    }

    int fusedBlocks = cdiv(N, TB / 32);
    int nScanBlocks = cdiv(N, 1024);

    // ---- build dst-sorted edge CSR ----
    detect_kernel<<<1, 1>>>(ei, 16, (long long)N);
    init_cnt_kernel<<<cdiv(N, TB), TB>>>(N);
    convert_hist_kernel<<<cdiv(E, TB), TB>>>(ei, E);
    scan1_kernel<<<nScanBlocks, 1024>>>(N);
    scan2_kernel<<<1, 32>>>(nScanBlocks);
    scan3_kernel<<<nScanBlocks, 1024>>>(N, TE);
    scatter_kernel<<<cdiv(TE, TB), TB>>>(E, TE);

    // ---- layer 1: dual GEMM (Nc=64) + fused GAT ----
    dim3 g1(2, cdiv(N, 128));
    dual_gemm_bf16<<<g1, TB, SMEM_GEMM>>>(x, Wl1, bl1, Wr1, br1, p_xlh, p_xr, N, 64);
    fused_gat_kernel<16, false><<<fusedBlocks, TB>>>(att1, bo1, p_h, N);

    // ---- layer 2: dual GEMM (Nc=256) + fused GAT ----
    dim3 g2(8, cdiv(N, 128));
    dual_gemm_bf16<<<g2, TB, SMEM_GEMM>>>(p_h, Wl2, bl2, Wr2, br2, p_xlh, p_xr, N, 256);
    fused_gat_kernel<64, true><<<fusedBlocks, TB>>>(att2, bo2, out, N);
}